// round 15
// baseline (speedup 1.0000x reference)
#include <cuda_runtime.h>
#include <cuda_fp16.h>
#include <cstdint>
#include <cstring>

// ---------------------------------------------------------------------------
// Shapes: T=S=512, B=64, D=512, H=5, QHD=32, PHD=4, PD=192
// fp16 hi/lo split intermediates in [b][t][col] layout.
// ---------------------------------------------------------------------------
static __device__ __half g_qh[64 * 512 * 160];
static __device__ __half g_ql[64 * 512 * 160];
static __device__ __half g_kh[64 * 512 * 160];
static __device__ __half g_kl[64 * 512 * 160];
static __device__ __half g_ph[64 * 512 * 20];    // p, fp16
static __device__ __half g_peh[5 * 1023 * 8];    // pe, fp16, [h][n][8] padded
static __device__ __half g_wh[2 * 192 * 512];    // pre-split W, [which][n][k]
static __device__ __half g_wl[2 * 192 * 512];

__device__ __forceinline__ uint32_t h2u(__half2 v) {
    uint32_t u;
    memcpy(&u, &v, 4);
    return u;
}
__device__ __forceinline__ uint32_t sptr(const void* p) {
    return (uint32_t)__cvta_generic_to_shared(p);
}
__device__ __forceinline__ void ldsm_x4(uint32_t a, uint32_t& r0, uint32_t& r1,
                                        uint32_t& r2, uint32_t& r3) {
    asm volatile("ldmatrix.sync.aligned.m8n8.x4.shared.b16 {%0,%1,%2,%3}, [%4];"
                 : "=r"(r0), "=r"(r1), "=r"(r2), "=r"(r3) : "r"(a));
}
__device__ __forceinline__ void ldsm_x2(uint32_t a, uint32_t& r0, uint32_t& r1) {
    asm volatile("ldmatrix.sync.aligned.m8n8.x2.shared.b16 {%0,%1}, [%2];"
                 : "=r"(r0), "=r"(r1) : "r"(a));
}
__device__ __forceinline__ void ldsm_x1(uint32_t a, uint32_t& r0) {
    asm volatile("ldmatrix.sync.aligned.m8n8.x1.shared.b16 {%0}, [%1];"
                 : "=r"(r0) : "r"(a));
}
__device__ __forceinline__ void mma_f16(float* c, const uint32_t* a, uint32_t b0, uint32_t b1) {
    asm volatile("mma.sync.aligned.m16n8k16.row.col.f32.f16.f16.f32 "
                 "{%0,%1,%2,%3},{%4,%5,%6,%7},{%8,%9},{%0,%1,%2,%3};"
                 : "+f"(c[0]), "+f"(c[1]), "+f"(c[2]), "+f"(c[3])
                 : "r"(a[0]), "r"(a[1]), "r"(a[2]), "r"(a[3]), "r"(b0), "r"(b1));
}
__device__ __forceinline__ void mma_f16_k8(float* c, const uint32_t* a, uint32_t b0) {
    asm volatile("mma.sync.aligned.m16n8k8.row.col.f32.f16.f16.f32 "
                 "{%0,%1,%2,%3},{%4,%5},{%6},{%0,%1,%2,%3};"
                 : "+f"(c[0]), "+f"(c[1]), "+f"(c[2]), "+f"(c[3])
                 : "r"(a[0]), "r"(a[1]), "r"(b0));
}
__device__ __forceinline__ void split_h(float x, __half& h, __half& l) {
    h = __float2half_rn(x);
    l = __float2half_rn(x - __half2float(h));
}
#define CP16(dst, src) asm volatile("cp.async.cg.shared.global [%0], [%1], 16;" \
                                    :: "r"(dst), "l"(src))

// ---------------------------------------------------------------------------
// Prep: W pre-split (blocks 0..95, 8 elements/thread)
//     + pe projection (blocks 96..415, 4 threads/output + shfl, fp16 padded out)
// ---------------------------------------------------------------------------
__global__ __launch_bounds__(256)
void prep_kernel(const float* __restrict__ W_lm, const float* __restrict__ W_am,
                 const float* __restrict__ pos, const float* __restrict__ Wp)
{
    if (blockIdx.x < 96) {
        const int base = (blockIdx.x * 256 + threadIdx.x) * 8;
        float v[8];
#pragma unroll
        for (int i = 0; i < 8; ++i) {
            const int idx = base + i;
            const int which = idx / 98304;
            const int r = idx % 98304;
            const int k = r / 192, col = r % 192;
            v[i] = 0.f;
            if (which == 0) { if (col < 180) v[i] = W_lm[k * 180 + col]; }
            else            { if (col < 160) v[i] = W_am[k * 160 + col]; }
        }
#pragma unroll
        for (int i = 0; i < 8; ++i) {
            const int idx = base + i;
            const int which = idx / 98304;
            const int r = idx % 98304;
            const int k = r / 192, col = r % 192;
            __half h, l;
            split_h(v[i], h, l);
            const int o = which * 98304 + col * 512 + k;
            g_wh[o] = h;
            g_wl[o] = l;
        }
    } else {
        const int idx = (blockIdx.x - 96) * 256 + threadIdx.x;
        if (idx >= 1023 * 20 * 4) return;
        const int pair = idx >> 2, sub = idx & 3;
        const int n = pair / 20, c = pair % 20;
        float s = 0.f;
#pragma unroll 12
        for (int dd = 0; dd < 48; ++dd)
            s = fmaf(pos[n * 192 + sub * 48 + dd], Wp[(sub * 48 + dd) * 20 + c], s);
        s += __shfl_xor_sync(0xffffffffu, s, 1);
        s += __shfl_xor_sync(0xffffffffu, s, 2);
        if (sub == 0) {
            const int h = c >> 2, d = c & 3;
            g_peh[((size_t)h * 1023 + n) * 8 + d] = __float2half_rn(s);
            if (d == 0)
                *(uint2*)&g_peh[((size_t)h * 1023 + n) * 8 + 4] = make_uint2(0u, 0u);
        }
    }
}

// ---------------------------------------------------------------------------
// Projection GEMM (fp16 3-term split). Both tensors in one launch (blockIdx.y).
// BM=128, BN=192, BK=32 double-buffered. B tiles via cp.async (pre-split fp16).
// Natural registers (no min-blocks cap — a 128-reg cap spills the mainloop).
// ---------------------------------------------------------------------------
#define PA 40
#define PBN 40
#define ASZ (128 * PA)
#define BSZ (192 * PBN)

__global__ __launch_bounds__(256)
void proj_mma3(const float* __restrict__ X_lm, const float* __restrict__ X_am,
               const float* __restrict__ b_lm, const float* __restrict__ b_am)
{
    extern __shared__ char sm[];
    __half* Ah = (__half*)sm;              // [2][ASZ]
    __half* Al = Ah + 2 * ASZ;
    __half* Bh = Al + 2 * ASZ;             // [2][BSZ]
    __half* Bl = Bh + 2 * BSZ;

    const int which = blockIdx.y;          // 0 = lm, 1 = am
    const float* X = which ? X_am : X_lm;
    const float* bias = which ? b_am : b_lm;
    const int N = which ? 160 : 180;
    const __half* Wh = g_wh + which * 98304;
    const __half* Wl = g_wl + which * 98304;

    const int tid = threadIdx.x;
    const int m0 = blockIdx.x * 128;
    const int w = tid >> 5, lane = tid & 31;
    const int wm = (w >> 1) * 32, wn = (w & 1) * 96;

    float4 aR[4];

    auto CPB = [&](int buf, int kt) {
#pragma unroll
        for (int i = 0; i < 3; ++i) {
            const int f = tid + 256 * i;          // < 768
            const int n = f >> 2, c = f & 3;
            CP16(sptr(&Bh[buf * BSZ + n * PBN + c * 8]), &Wh[n * 512 + kt + c * 8]);
            CP16(sptr(&Bl[buf * BSZ + n * PBN + c * 8]), &Wl[n * 512 + kt + c * 8]);
        }
    };
    auto LDGA = [&](int kt) {
#pragma unroll
        for (int i = 0; i < 4; ++i) {
            const int f = tid + 256 * i;
            aR[i] = *(const float4*)&X[(size_t)(m0 + (f >> 3)) * 512 + kt + (f & 7) * 4];
        }
    };
    auto STSA = [&](int buf) {
#pragma unroll
        for (int i = 0; i < 4; ++i) {
            const int f = tid + 256 * i;
            const int row = f >> 3, kc = (f & 7) * 4;
            __half h0, l0, h1, l1, h2, l2, h3, l3;
            split_h(aR[i].x, h0, l0); split_h(aR[i].y, h1, l1);
            split_h(aR[i].z, h2, l2); split_h(aR[i].w, h3, l3);
            *(ushort4*)&Ah[buf * ASZ + row * PA + kc] = make_ushort4(
                __half_as_ushort(h0), __half_as_ushort(h1),
                __half_as_ushort(h2), __half_as_ushort(h3));
            *(ushort4*)&Al[buf * ASZ + row * PA + kc] = make_ushort4(
                __half_as_ushort(l0), __half_as_ushort(l1),
                __half_as_ushort(l2), __half_as_ushort(l3));
        }
    };

    float acc[2][12][4];
#pragma unroll
    for (int mt = 0; mt < 2; ++mt)
#pragma unroll
        for (int nt = 0; nt < 12; ++nt)
#pragma unroll
            for (int c = 0; c < 4; ++c) acc[mt][nt][c] = 0.f;

    CPB(0, 0);
    asm volatile("cp.async.commit_group;");
    LDGA(0);
    STSA(0);
    asm volatile("cp.async.wait_group 0;");
    __syncthreads();

    for (int s = 0; s < 16; ++s) {
        const int cur = s & 1;
        if (s < 15) {
            CPB(cur ^ 1, (s + 1) * 32);
            asm volatile("cp.async.commit_group;");
            LDGA((s + 1) * 32);
        }
#pragma unroll
        for (int ks = 0; ks < 2; ++ks) {
            uint32_t ah[2][4], al[2][4];
#pragma unroll
            for (int mt = 0; mt < 2; ++mt) {
                const int ro = (wm + mt * 16 + (lane & 15)) * PA + ks * 16 + ((lane >> 4) & 1) * 8;
                ldsm_x4(sptr(&Ah[cur * ASZ + ro]), ah[mt][0], ah[mt][1], ah[mt][2], ah[mt][3]);
                ldsm_x4(sptr(&Al[cur * ASZ + ro]), al[mt][0], al[mt][1], al[mt][2], al[mt][3]);
            }
#pragma unroll
            for (int ntp = 0; ntp < 6; ++ntp) {
                uint32_t bh[4], bl[4];
                const int ro = (wn + ntp * 16 + (lane & 7) + ((lane >> 4) & 1) * 8) * PBN
                             + ks * 16 + ((lane >> 3) & 1) * 8;
                ldsm_x4(sptr(&Bh[cur * BSZ + ro]), bh[0], bh[1], bh[2], bh[3]);
                ldsm_x4(sptr(&Bl[cur * BSZ + ro]), bl[0], bl[1], bl[2], bl[3]);
#pragma unroll
                for (int sub = 0; sub < 2; ++sub) {
                    const int q = sub * 2;
#pragma unroll
                    for (int mt = 0; mt < 2; ++mt) {
                        float* a4 = acc[mt][ntp * 2 + sub];
                        mma_f16(a4, al[mt], bh[q], bh[q + 1]);
                        mma_f16(a4, ah[mt], bl[q], bl[q + 1]);
                        mma_f16(a4, ah[mt], bh[q], bh[q + 1]);
                    }
                }
            }
        }
        if (s < 15) {
            STSA(cur ^ 1);
            asm volatile("cp.async.wait_group 0;");
            __syncthreads();
        }
    }

    // ---- epilogue: bias add, split fp16, route to globals
#pragma unroll
    for (int mt = 0; mt < 2; ++mt) {
        const int r = m0 + wm + mt * 16 + (lane >> 2);
#pragma unroll
        for (int nt = 0; nt < 12; ++nt) {
            const int col = wn + nt * 8 + (lane & 3) * 2;
            if (col >= N) continue;
            const float b0 = bias[col], b1 = bias[col + 1];
            const float v[4] = {acc[mt][nt][0] + b0, acc[mt][nt][1] + b1,
                                acc[mt][nt][2] + b0, acc[mt][nt][3] + b1};
#pragma unroll
            for (int half_ = 0; half_ < 2; ++half_) {
                const int rr = r + half_ * 8;
                const int t = rr >> 6, bb = rr & 63;
                const float x0 = v[half_ * 2], x1 = v[half_ * 2 + 1];
                if (col < 160) {
                    const size_t o = ((size_t)(bb << 9) + t) * 160 + col;
                    __half h0, l0, h1, l1;
                    split_h(x0, h0, l0); split_h(x1, h1, l1);
                    if (which == 0) {
                        *(ushort2*)&g_qh[o] = make_ushort2(__half_as_ushort(h0), __half_as_ushort(h1));
                        *(ushort2*)&g_ql[o] = make_ushort2(__half_as_ushort(l0), __half_as_ushort(l1));
                    } else {
                        *(ushort2*)&g_kh[o] = make_ushort2(__half_as_ushort(h0), __half_as_ushort(h1));
                        *(ushort2*)&g_kl[o] = make_ushort2(__half_as_ushort(l0), __half_as_ushort(l1));
                    }
                } else if (which == 0) {
                    *(__half2*)&g_ph[((size_t)(bb << 9) + t) * 20 + col - 160] =
                        __floats2half2_rn(x0, x1);
                }
            }
        }
    }
}

// ---------------------------------------------------------------------------
// Attention weights. Block = one 128x512 tile of one (b,h). Grid (4,64,5).
// Four 32-row iterations over a shared K tile (loaded ONCE).
// 512 threads = 16 warps; warp w owns cols [w*32, w*32+32).
// Band phase write base = 112 - iter*32 - mt*16; reader m = col + 15 - r16.
// peW = 640 rows (reads past it feed only provably-unread band entries).
// smem 114560 B -> 112KB granule -> 2 CTAs/SM.
// ---------------------------------------------------------------------------
#define PEP 8
#define BANDP 552
#define PEROWS3 640

#define SWZ(r, c) ((c) ^ (((r) >> 1) & 3))

// smem layout in halves
#define SM_KH   0
#define SM_KL   (512 * 32)
#define SM_QH   (2 * 512 * 32)
#define SM_QL   (2 * 512 * 32 + 128 * 32)
#define SM_PEW  (2 * 512 * 32 + 2 * 128 * 32)
#define SM_PSA  (SM_PEW + PEROWS3 * PEP)
#define SM_BAND (SM_PSA + 128 * PEP)
#define SM_HALVES (SM_BAND + 16 * BANDP)

__global__ __launch_bounds__(512, 2)
void attn_kernel(const unsigned char* __restrict__ mask, float* __restrict__ out)
{
    extern __shared__ __half sh[];
    __half* Kh   = sh + SM_KH;
    __half* Kl   = sh + SM_KL;
    __half* Qh   = sh + SM_QH;                        // [128][32]
    __half* Ql   = sh + SM_QL;
    __half* peW  = sh + SM_PEW;                       // [640][8]
    __half* psA  = sh + SM_PSA;                       // [128][8]
    __half* band = sh + SM_BAND;                      // [16][BANDP], phased
    float* redS  = (float*)(sh + SM_HALVES);          // [32][16]
    float* ginv  = redS + 512;                        // [32]
    unsigned char* msk = (unsigned char*)(ginv + 32); // [512]

    const int t0b = blockIdx.x * 128;
    const int b   = blockIdx.y;
    const int h   = blockIdx.z;
    const int tid = threadIdx.x;
    const int w = tid >> 5, lane = tid & 31;

    // ---- one-shot load phase: K + pe via cp.async, Q (all rows), p, mask
#pragma unroll
    for (int s = 0; s < 4; ++s) {
        const int it = tid + 512 * s;               // 0..2047
        const int j = it >> 2, c = it & 3;
        const __half* srcH = g_kh + ((size_t)(b << 9) + j) * 160 + h * 32 + c * 8;
        const __half* srcL = g_kl + ((size_t)(b << 9) + j) * 160 + h * 32 + c * 8;
        CP16(sptr(&Kh[j * 32 + SWZ(j, c) * 8]), srcH);
        CP16(sptr(&Kl[j * 32 + SWZ(j, c) * 8]), srcL);
    }
    for (int j = tid; j < PEROWS3; j += 512) {
        const int n = 384 - t0b + j;                // >= 0 for t0b <= 384
        if (n <= 1022) {
            CP16(sptr(&peW[j * PEP]), g_peh + ((size_t)h * 1023 + n) * 8);
        } else {
            *(uint4*)&peW[j * PEP] = make_uint4(0u, 0u, 0u, 0u);
        }
    }
    asm volatile("cp.async.commit_group;");

#pragma unroll
    for (int s = 0; s < 2; ++s) {                   // Q: 1024 uint4 assignments
        const int idx = tid + 512 * s;
        const int part = idx >> 9, r = (idx >> 2) & 127, c = idx & 3;
        const size_t o = ((size_t)(b << 9) + t0b + r) * 160 + h * 32 + c * 8;
        __half* dst = part ? Ql : Qh;
        const __half* src = part ? g_ql : g_qh;
        *(uint4*)&dst[r * 32 + SWZ(r, c) * 8] = *(const uint4*)(src + o);
    }
    if (tid < 128) {
        const uint2 u = *(const uint2*)&g_ph[((size_t)(b << 9) + t0b + tid) * 20 + h * 4];
        *(uint4*)&psA[tid * PEP] = make_uint4(u.x, u.y, 0u, 0u);
    }
    msk[tid & 511] = mask[b * 512 + (tid & 511)];
    asm volatile("cp.async.wait_group 0;");
    __syncthreads();

#pragma unroll 1
    for (int iter = 0; iter < 4; ++iter) {
        // ---- content QK^T (fp16 3-term), swizzled ldmatrix
        float acc[2][4][4];
#pragma unroll
        for (int mt = 0; mt < 2; ++mt)
#pragma unroll
            for (int nt = 0; nt < 4; ++nt)
#pragma unroll
                for (int c = 0; c < 4; ++c) acc[mt][nt][c] = 0.f;

#pragma unroll
        for (int ks = 0; ks < 2; ++ks) {
            uint32_t ah[2][4], al[2][4];
#pragma unroll
            for (int mt = 0; mt < 2; ++mt) {
                const int row = iter * 32 + mt * 16 + (lane & 15);
                const int ch = ks * 2 + ((lane >> 4) & 1);
                const int ro = row * 32 + SWZ(row, ch) * 8;
                ldsm_x4(sptr(&Qh[ro]), ah[mt][0], ah[mt][1], ah[mt][2], ah[mt][3]);
                ldsm_x4(sptr(&Ql[ro]), al[mt][0], al[mt][1], al[mt][2], al[mt][3]);
            }
#pragma unroll
            for (int ntp = 0; ntp < 2; ++ntp) {
                uint32_t bh[4], bl[4];
                const int row = w * 32 + ntp * 16 + (lane & 7) + ((lane >> 4) & 1) * 8;
                const int ch = ks * 2 + ((lane >> 3) & 1);
                const int ro = row * 32 + SWZ(row, ch) * 8;
                ldsm_x4(sptr(&Kh[ro]), bh[0], bh[1], bh[2], bh[3]);
                ldsm_x4(sptr(&Kl[ro]), bl[0], bl[1], bl[2], bl[3]);
#pragma unroll
                for (int sub = 0; sub < 2; ++sub) {
                    const int q = sub * 2;
#pragma unroll
                    for (int mt = 0; mt < 2; ++mt) {
                        float* a4 = acc[mt][ntp * 2 + sub];
                        mma_f16(a4, al[mt], bh[q], bh[q + 1]);
                        mma_f16(a4, ah[mt], bl[q], bl[q + 1]);
                        mma_f16(a4, ah[mt], bh[q], bh[q + 1]);
                    }
                }
            }
        }

        // ---- phased: band (16 rows) -> gather/exp/sum for that mt
#pragma unroll
        for (int mt = 0; mt < 2; ++mt) {
            const int base = 112 - iter * 32 - mt * 16;   // >= 0 for all phases
            uint32_t pa[2];
            ldsm_x2(sptr(&psA[(iter * 32 + mt * 16 + (lane & 15)) * PEP]), pa[0], pa[1]);
#pragma unroll
            for (int tp = 0; tp < 2; ++tp) {
                const int tb = w * 4 + tp * 2;
                uint32_t b2[2];
                ldsm_x2(sptr(&peW[(base + tb * 8 + (lane & 15)) * PEP]), b2[0], b2[1]);
#pragma unroll
                for (int tt = 0; tt < 2; ++tt) {
                    const int nn = (tb + tt) * 8 + (lane & 3) * 2;
                    float bc[4] = {0.f, 0.f, 0.f, 0.f};
                    mma_f16_k8(bc, pa, b2[tt]);
                    const int r16 = lane >> 2;
                    *(uint32_t*)&band[r16 * BANDP + nn] =
                        h2u(__floats2half2_rn(bc[0], bc[1]));
                    *(uint32_t*)&band[(r16 + 8) * BANDP + nn] =
                        h2u(__floats2half2_rn(bc[2], bc[3]));
                }
            }
            if (w < 4) {                             // tiles 64..67
                const int t = 64 + w;
                uint32_t b1;
                ldsm_x1(sptr(&peW[(base + t * 8 + (lane & 7)) * PEP]), b1);
                const int nn = t * 8 + (lane & 3) * 2;
                float bc[4] = {0.f, 0.f, 0.f, 0.f};
                mma_f16_k8(bc, pa, b1);
                const int r16 = lane >> 2;
                *(uint32_t*)&band[r16 * BANDP + nn] =
                    h2u(__floats2half2_rn(bc[0], bc[1]));
                *(uint32_t*)&band[(r16 + 8) * BANDP + nn] =
                    h2u(__floats2half2_rn(bc[2], bc[3]));
            }
            __syncthreads();

            // epilogue for this mt: band read m = col + 15 - r16
#pragma unroll
            for (int cp = 0; cp < 2; ++cp) {
                const int rl = mt * 16 + cp * 8 + (lane >> 2);   // 0..31 within iter
                const int r16 = cp * 8 + (lane >> 2);            // 0..15
                float s = 0.f;
#pragma unroll
                for (int nt = 0; nt < 4; ++nt)
#pragma unroll
                    for (int cc = 0; cc < 2; ++cc) {
                        const int col = w * 32 + nt * 8 + (lane & 3) * 2 + cc;
                        float v = acc[mt][nt][cp * 2 + cc]
                                + __half2float(band[r16 * BANDP + col + 15 - r16]);
                        if (msk[col]) v = -1000.f;
                        v = __expf(v);
                        acc[mt][nt][cp * 2 + cc] = v;
                        s += v;
                    }
                s += __shfl_xor_sync(0xffffffffu, s, 1);
                s += __shfl_xor_sync(0xffffffffu, s, 2);
                if ((lane & 3) == 0) redS[rl * 16 + w] = s;
            }
            __syncthreads();
        }

        // ---- final row-sum reduce for this iter
        {
            float v = redS[tid];
            v += __shfl_xor_sync(0xffffffffu, v, 1);
            v += __shfl_xor_sync(0xffffffffu, v, 2);
            v += __shfl_xor_sync(0xffffffffu, v, 4);
            v += __shfl_xor_sync(0xffffffffu, v, 8);
            if ((tid & 15) == 0) ginv[tid >> 4] = 1.f / v;
        }
        __syncthreads();

        // ---- scale + store for this iter
#pragma unroll
        for (int mt = 0; mt < 2; ++mt)
#pragma unroll
            for (int cp = 0; cp < 2; ++cp) {
                const int rl = mt * 16 + cp * 8 + (lane >> 2);
                const float iv = ginv[rl];
                const size_t base_o =
                    (((size_t)h * 64 + b) * 512 + t0b + iter * 32 + rl) * 512;
#pragma unroll
                for (int nt = 0; nt < 4; ++nt) {
                    float2 o;
                    o.x = acc[mt][nt][cp * 2 + 0] * iv;
                    o.y = acc[mt][nt][cp * 2 + 1] * iv;
                    *(float2*)&out[base_o + w * 32 + nt * 8 + (lane & 3) * 2] = o;
                }
            }
        __syncthreads();
    }
}

// ---------------------------------------------------------------------------
extern "C" void kernel_launch(void* const* d_in, const int* in_sizes, int n_in,
                              void* d_out, int out_size)
{
    const float* lm_pruned = (const float*)d_in[0];
    const float* am_pruned = (const float*)d_in[1];
    const float* pos_emb   = (const float*)d_in[2];
    const unsigned char* kpm = (const unsigned char*)d_in[3];
    const float* W_lm  = (const float*)d_in[4];
    const float* b_lm  = (const float*)d_in[5];
    const float* W_am  = (const float*)d_in[6];
    const float* b_am  = (const float*)d_in[7];
    const float* W_pos = (const float*)d_in[8];
    float* out = (float*)d_out;

    prep_kernel<<<416, 256>>>(W_lm, W_am, pos_emb, W_pos);

    const int proj_smem = (2 * ASZ + 2 * BSZ) * 2 * 2;   // 102400 bytes
    cudaFuncSetAttribute(proj_mma3, cudaFuncAttributeMaxDynamicSharedMemorySize, proj_smem);
    proj_mma3<<<dim3(256, 2), 256, proj_smem>>>(lm_pruned, am_pruned, b_lm, b_am);

    const int attn_smem = SM_HALVES * 2            // half arrays (111872 B)
                        + 512 * 4 + 32 * 4 + 512;  // redS, ginv, mask -> 114560 B
    cudaFuncSetAttribute(attn_kernel, cudaFuncAttributeMaxDynamicSharedMemorySize, attn_smem);
    attn_kernel<<<dim3(4, 64, 5), 512, attn_smem>>>(kpm, out);
}

// round 16
// speedup vs baseline: 1.0399x; 1.0399x over previous
#include <cuda_runtime.h>
#include <cuda_fp16.h>
#include <cstdint>
#include <cstring>

// ---------------------------------------------------------------------------
// Shapes: T=S=512, B=64, D=512, H=5, QHD=32, PHD=4, PD=192
// fp16 hi/lo split intermediates in [b][t][col] layout.
// ---------------------------------------------------------------------------
static __device__ __half g_qh[64 * 512 * 160];
static __device__ __half g_ql[64 * 512 * 160];
static __device__ __half g_kh[64 * 512 * 160];
static __device__ __half g_kl[64 * 512 * 160];
static __device__ __half g_ph[64 * 512 * 20];    // p, fp16
static __device__ __half g_peh[5 * 1023 * 8];    // pe, fp16, [h][n][8] padded
static __device__ __half g_wh[2 * 192 * 512];    // pre-split W, [which][n][k]
static __device__ __half g_wl[2 * 192 * 512];

__device__ __forceinline__ uint32_t h2u(__half2 v) {
    uint32_t u;
    memcpy(&u, &v, 4);
    return u;
}
__device__ __forceinline__ uint32_t sptr(const void* p) {
    return (uint32_t)__cvta_generic_to_shared(p);
}
__device__ __forceinline__ void ldsm_x4(uint32_t a, uint32_t& r0, uint32_t& r1,
                                        uint32_t& r2, uint32_t& r3) {
    asm volatile("ldmatrix.sync.aligned.m8n8.x4.shared.b16 {%0,%1,%2,%3}, [%4];"
                 : "=r"(r0), "=r"(r1), "=r"(r2), "=r"(r3) : "r"(a));
}
__device__ __forceinline__ void ldsm_x2(uint32_t a, uint32_t& r0, uint32_t& r1) {
    asm volatile("ldmatrix.sync.aligned.m8n8.x2.shared.b16 {%0,%1}, [%2];"
                 : "=r"(r0), "=r"(r1) : "r"(a));
}
__device__ __forceinline__ void ldsm_x1(uint32_t a, uint32_t& r0) {
    asm volatile("ldmatrix.sync.aligned.m8n8.x1.shared.b16 {%0}, [%1];"
                 : "=r"(r0) : "r"(a));
}
__device__ __forceinline__ void mma_f16(float* c, const uint32_t* a, uint32_t b0, uint32_t b1) {
    asm volatile("mma.sync.aligned.m16n8k16.row.col.f32.f16.f16.f32 "
                 "{%0,%1,%2,%3},{%4,%5,%6,%7},{%8,%9},{%0,%1,%2,%3};"
                 : "+f"(c[0]), "+f"(c[1]), "+f"(c[2]), "+f"(c[3])
                 : "r"(a[0]), "r"(a[1]), "r"(a[2]), "r"(a[3]), "r"(b0), "r"(b1));
}
__device__ __forceinline__ void mma_f16_k8(float* c, const uint32_t* a, uint32_t b0) {
    asm volatile("mma.sync.aligned.m16n8k8.row.col.f32.f16.f16.f32 "
                 "{%0,%1,%2,%3},{%4,%5},{%6},{%0,%1,%2,%3};"
                 : "+f"(c[0]), "+f"(c[1]), "+f"(c[2]), "+f"(c[3])
                 : "r"(a[0]), "r"(a[1]), "r"(b0));
}
__device__ __forceinline__ void split_h(float x, __half& h, __half& l) {
    h = __float2half_rn(x);
    l = __float2half_rn(x - __half2float(h));
}
#define CP16(dst, src) asm volatile("cp.async.cg.shared.global [%0], [%1], 16;" \
                                    :: "r"(dst), "l"(src))

// ---------------------------------------------------------------------------
// Prep: W pre-split ONLY (96 blocks, 8 elements/thread). pe moved into proj.
// ---------------------------------------------------------------------------
__global__ __launch_bounds__(256)
void prep_kernel(const float* __restrict__ W_lm, const float* __restrict__ W_am)
{
    const int base = (blockIdx.x * 256 + threadIdx.x) * 8;
    float v[8];
#pragma unroll
    for (int i = 0; i < 8; ++i) {
        const int idx = base + i;
        const int which = idx / 98304;
        const int r = idx % 98304;
        const int k = r / 192, col = r % 192;
        v[i] = 0.f;
        if (which == 0) { if (col < 180) v[i] = W_lm[k * 180 + col]; }
        else            { if (col < 160) v[i] = W_am[k * 160 + col]; }
    }
#pragma unroll
    for (int i = 0; i < 8; ++i) {
        const int idx = base + i;
        const int which = idx / 98304;
        const int r = idx % 98304;
        const int k = r / 192, col = r % 192;
        __half h, l;
        split_h(v[i], h, l);
        const int o = which * 98304 + col * 512 + k;
        g_wh[o] = h;
        g_wl[o] = l;
    }
}

// ---------------------------------------------------------------------------
// Projection GEMM (fp16 3-term split). blockIdx.y: 0 = lm, 1 = am,
// 2 = pe projection (light blocks, hidden under the heavy GEMM blocks).
// BM=128, BN=192, BK=32 double-buffered. B tiles via cp.async (pre-split fp16).
// ---------------------------------------------------------------------------
#define PA 40
#define PBN 40
#define ASZ (128 * PA)
#define BSZ (192 * PBN)

__global__ __launch_bounds__(256)
void proj_mma3(const float* __restrict__ X_lm, const float* __restrict__ X_am,
               const float* __restrict__ b_lm, const float* __restrict__ b_am,
               const float* __restrict__ pos, const float* __restrict__ Wp)
{
    const int which = blockIdx.y;

    if (which == 2) {                      // ---- pe projection slice
        const int idx = blockIdx.x * 256 + threadIdx.x;
        if (idx >= 1023 * 20) return;
        const int n = idx / 20;
        const int c = idx % 20;
        float s = 0.f;
#pragma unroll 8
        for (int d = 0; d < 192; ++d)
            s = fmaf(pos[n * 192 + d], Wp[d * 20 + c], s);
        const int hh = c >> 2, dd = c & 3;
        g_peh[((size_t)hh * 1023 + n) * 8 + dd] = __float2half_rn(s);
        if (dd == 0)
            *(uint2*)&g_peh[((size_t)hh * 1023 + n) * 8 + 4] = make_uint2(0u, 0u);
        return;
    }

    extern __shared__ char sm[];
    __half* Ah = (__half*)sm;              // [2][ASZ]
    __half* Al = Ah + 2 * ASZ;
    __half* Bh = Al + 2 * ASZ;             // [2][BSZ]
    __half* Bl = Bh + 2 * BSZ;

    const float* X = which ? X_am : X_lm;
    const float* bias = which ? b_am : b_lm;
    const int N = which ? 160 : 180;
    const __half* Wh = g_wh + which * 98304;
    const __half* Wl = g_wl + which * 98304;

    const int tid = threadIdx.x;
    const int m0 = blockIdx.x * 128;
    const int w = tid >> 5, lane = tid & 31;
    const int wm = (w >> 1) * 32, wn = (w & 1) * 96;

    float4 aR[4];

    auto CPB = [&](int buf, int kt) {
#pragma unroll
        for (int i = 0; i < 3; ++i) {
            const int f = tid + 256 * i;          // < 768
            const int n = f >> 2, c = f & 3;
            CP16(sptr(&Bh[buf * BSZ + n * PBN + c * 8]), &Wh[n * 512 + kt + c * 8]);
            CP16(sptr(&Bl[buf * BSZ + n * PBN + c * 8]), &Wl[n * 512 + kt + c * 8]);
        }
    };
    auto LDGA = [&](int kt) {
#pragma unroll
        for (int i = 0; i < 4; ++i) {
            const int f = tid + 256 * i;
            aR[i] = *(const float4*)&X[(size_t)(m0 + (f >> 3)) * 512 + kt + (f & 7) * 4];
        }
    };
    auto STSA = [&](int buf) {
#pragma unroll
        for (int i = 0; i < 4; ++i) {
            const int f = tid + 256 * i;
            const int row = f >> 3, kc = (f & 7) * 4;
            __half h0, l0, h1, l1, h2, l2, h3, l3;
            split_h(aR[i].x, h0, l0); split_h(aR[i].y, h1, l1);
            split_h(aR[i].z, h2, l2); split_h(aR[i].w, h3, l3);
            *(ushort4*)&Ah[buf * ASZ + row * PA + kc] = make_ushort4(
                __half_as_ushort(h0), __half_as_ushort(h1),
                __half_as_ushort(h2), __half_as_ushort(h3));
            *(ushort4*)&Al[buf * ASZ + row * PA + kc] = make_ushort4(
                __half_as_ushort(l0), __half_as_ushort(l1),
                __half_as_ushort(l2), __half_as_ushort(l3));
        }
    };

    float acc[2][12][4];
#pragma unroll
    for (int mt = 0; mt < 2; ++mt)
#pragma unroll
        for (int nt = 0; nt < 12; ++nt)
#pragma unroll
            for (int c = 0; c < 4; ++c) acc[mt][nt][c] = 0.f;

    CPB(0, 0);
    asm volatile("cp.async.commit_group;");
    LDGA(0);
    STSA(0);
    asm volatile("cp.async.wait_group 0;");
    __syncthreads();

    for (int s = 0; s < 16; ++s) {
        const int cur = s & 1;
        if (s < 15) {
            CPB(cur ^ 1, (s + 1) * 32);
            asm volatile("cp.async.commit_group;");
            LDGA((s + 1) * 32);
        }
#pragma unroll
        for (int ks = 0; ks < 2; ++ks) {
            uint32_t ah[2][4], al[2][4];
#pragma unroll
            for (int mt = 0; mt < 2; ++mt) {
                const int ro = (wm + mt * 16 + (lane & 15)) * PA + ks * 16 + ((lane >> 4) & 1) * 8;
                ldsm_x4(sptr(&Ah[cur * ASZ + ro]), ah[mt][0], ah[mt][1], ah[mt][2], ah[mt][3]);
                ldsm_x4(sptr(&Al[cur * ASZ + ro]), al[mt][0], al[mt][1], al[mt][2], al[mt][3]);
            }
#pragma unroll
            for (int ntp = 0; ntp < 6; ++ntp) {
                uint32_t bh[4], bl[4];
                const int ro = (wn + ntp * 16 + (lane & 7) + ((lane >> 4) & 1) * 8) * PBN
                             + ks * 16 + ((lane >> 3) & 1) * 8;
                ldsm_x4(sptr(&Bh[cur * BSZ + ro]), bh[0], bh[1], bh[2], bh[3]);
                ldsm_x4(sptr(&Bl[cur * BSZ + ro]), bl[0], bl[1], bl[2], bl[3]);
#pragma unroll
                for (int sub = 0; sub < 2; ++sub) {
                    const int q = sub * 2;
#pragma unroll
                    for (int mt = 0; mt < 2; ++mt) {
                        float* a4 = acc[mt][ntp * 2 + sub];
                        mma_f16(a4, al[mt], bh[q], bh[q + 1]);
                        mma_f16(a4, ah[mt], bl[q], bl[q + 1]);
                        mma_f16(a4, ah[mt], bh[q], bh[q + 1]);
                    }
                }
            }
        }
        if (s < 15) {
            STSA(cur ^ 1);
            asm volatile("cp.async.wait_group 0;");
            __syncthreads();
        }
    }

    // ---- epilogue: bias add, split fp16, route to globals
#pragma unroll
    for (int mt = 0; mt < 2; ++mt) {
        const int r = m0 + wm + mt * 16 + (lane >> 2);
#pragma unroll
        for (int nt = 0; nt < 12; ++nt) {
            const int col = wn + nt * 8 + (lane & 3) * 2;
            if (col >= N) continue;
            const float b0 = bias[col], b1 = bias[col + 1];
            const float v[4] = {acc[mt][nt][0] + b0, acc[mt][nt][1] + b1,
                                acc[mt][nt][2] + b0, acc[mt][nt][3] + b1};
#pragma unroll
            for (int half_ = 0; half_ < 2; ++half_) {
                const int rr = r + half_ * 8;
                const int t = rr >> 6, bb = rr & 63;
                const float x0 = v[half_ * 2], x1 = v[half_ * 2 + 1];
                if (col < 160) {
                    const size_t o = ((size_t)(bb << 9) + t) * 160 + col;
                    __half h0, l0, h1, l1;
                    split_h(x0, h0, l0); split_h(x1, h1, l1);
                    if (which == 0) {
                        *(ushort2*)&g_qh[o] = make_ushort2(__half_as_ushort(h0), __half_as_ushort(h1));
                        *(ushort2*)&g_ql[o] = make_ushort2(__half_as_ushort(l0), __half_as_ushort(l1));
                    } else {
                        *(ushort2*)&g_kh[o] = make_ushort2(__half_as_ushort(h0), __half_as_ushort(h1));
                        *(ushort2*)&g_kl[o] = make_ushort2(__half_as_ushort(l0), __half_as_ushort(l1));
                    }
                } else if (which == 0) {
                    *(__half2*)&g_ph[((size_t)(bb << 9) + t) * 20 + col - 160] =
                        __floats2half2_rn(x0, x1);
                }
            }
        }
    }
}

// ---------------------------------------------------------------------------
// Attention weights (R13 config). Block = one 64x512 tile of one (b,h).
// Grid (8,64,5). Two 32-row halves iterate over a shared K tile (loaded ONCE).
// 512 threads = 16 warps; warp w owns cols [w*32, w*32+32).
// Streaming (__stcs) output stores. ~104.6 KB smem -> 2 CTAs/SM.
// ---------------------------------------------------------------------------
#define PEP 8
#define BANDP 552
#define PEROWS2 592

#define SWZ(r, c) ((c) ^ (((r) >> 1) & 3))

// smem layout in halves
#define SM_KH   0
#define SM_KL   (512 * 32)
#define SM_QH   (2 * 512 * 32)
#define SM_QL   (2 * 512 * 32 + 64 * 32)
#define SM_PEW  (2 * 512 * 32 + 2 * 64 * 32)
#define SM_PSA  (SM_PEW + PEROWS2 * PEP)
#define SM_BAND (SM_PSA + 64 * PEP)
#define SM_HALVES (SM_BAND + 16 * BANDP)

__global__ __launch_bounds__(512, 2)
void attn_kernel(const unsigned char* __restrict__ mask, float* __restrict__ out)
{
    extern __shared__ __half sh[];
    __half* Kh   = sh + SM_KH;
    __half* Kl   = sh + SM_KL;
    __half* Qh   = sh + SM_QH;                        // [64][32]
    __half* Ql   = sh + SM_QL;
    __half* peW  = sh + SM_PEW;                       // [592][8]
    __half* psA  = sh + SM_PSA;                       // [64][8]
    __half* band = sh + SM_BAND;                      // [16][BANDP], phased
    float* redS  = (float*)(sh + SM_HALVES);          // [32][16]
    float* ginv  = redS + 512;                        // [32]
    unsigned char* msk = (unsigned char*)(ginv + 32); // [512]

    const int t0b = blockIdx.x * 64;
    const int b   = blockIdx.y;
    const int h   = blockIdx.z;
    const int tid = threadIdx.x;
    const int w = tid >> 5, lane = tid & 31;

    // ---- one-shot load phase: K + pe via cp.async, Q (both halves), p, mask
#pragma unroll
    for (int s = 0; s < 4; ++s) {
        const int it = tid + 512 * s;               // 0..2047
        const int j = it >> 2, c = it & 3;
        const __half* srcH = g_kh + ((size_t)(b << 9) + j) * 160 + h * 32 + c * 8;
        const __half* srcL = g_kl + ((size_t)(b << 9) + j) * 160 + h * 32 + c * 8;
        CP16(sptr(&Kh[j * 32 + SWZ(j, c) * 8]), srcH);
        CP16(sptr(&Kl[j * 32 + SWZ(j, c) * 8]), srcL);
    }
    for (int j = tid; j < PEROWS2; j += 512) {
        const int n = 448 - t0b + j;                // >= 0 always
        if (n <= 1022) {
            CP16(sptr(&peW[j * PEP]), g_peh + ((size_t)h * 1023 + n) * 8);
        } else {
            *(uint4*)&peW[j * PEP] = make_uint4(0u, 0u, 0u, 0u);
        }
    }
    asm volatile("cp.async.commit_group;");

    {   // Q: 2 parts x 64 rows x 4 chunks = 512 assignments
        const int part = tid >> 8, r = (tid >> 2) & 63, c = tid & 3;
        const size_t o = ((size_t)(b << 9) + t0b + r) * 160 + h * 32 + c * 8;
        __half* dst = part ? Ql : Qh;
        const __half* src = part ? g_ql : g_qh;
        *(uint4*)&dst[r * 32 + SWZ(r, c) * 8] = *(const uint4*)(src + o);
    }
    if (tid < 64) {
        const uint2 u = *(const uint2*)&g_ph[((size_t)(b << 9) + t0b + tid) * 20 + h * 4];
        *(uint4*)&psA[tid * PEP] = make_uint4(u.x, u.y, 0u, 0u);
    }
    msk[tid & 511] = mask[b * 512 + (tid & 511)];
    asm volatile("cp.async.wait_group 0;");
    __syncthreads();

#pragma unroll 1
    for (int iter = 0; iter < 2; ++iter) {
        // ---- content QK^T (fp16 3-term), swizzled ldmatrix
        float acc[2][4][4];
#pragma unroll
        for (int mt = 0; mt < 2; ++mt)
#pragma unroll
            for (int nt = 0; nt < 4; ++nt)
#pragma unroll
                for (int c = 0; c < 4; ++c) acc[mt][nt][c] = 0.f;

#pragma unroll
        for (int ks = 0; ks < 2; ++ks) {
            uint32_t ah[2][4], al[2][4];
#pragma unroll
            for (int mt = 0; mt < 2; ++mt) {
                const int row = iter * 32 + mt * 16 + (lane & 15);
                const int ch = ks * 2 + ((lane >> 4) & 1);
                const int ro = row * 32 + SWZ(row, ch) * 8;
                ldsm_x4(sptr(&Qh[ro]), ah[mt][0], ah[mt][1], ah[mt][2], ah[mt][3]);
                ldsm_x4(sptr(&Ql[ro]), al[mt][0], al[mt][1], al[mt][2], al[mt][3]);
            }
#pragma unroll
            for (int ntp = 0; ntp < 2; ++ntp) {
                uint32_t bh[4], bl[4];
                const int row = w * 32 + ntp * 16 + (lane & 7) + ((lane >> 4) & 1) * 8;
                const int ch = ks * 2 + ((lane >> 3) & 1);
                const int ro = row * 32 + SWZ(row, ch) * 8;
                ldsm_x4(sptr(&Kh[ro]), bh[0], bh[1], bh[2], bh[3]);
                ldsm_x4(sptr(&Kl[ro]), bl[0], bl[1], bl[2], bl[3]);
#pragma unroll
                for (int sub = 0; sub < 2; ++sub) {
                    const int q = sub * 2;
#pragma unroll
                    for (int mt = 0; mt < 2; ++mt) {
                        float* a4 = acc[mt][ntp * 2 + sub];
                        mma_f16(a4, al[mt], bh[q], bh[q + 1]);
                        mma_f16(a4, ah[mt], bl[q], bl[q + 1]);
                        mma_f16(a4, ah[mt], bh[q], bh[q + 1]);
                    }
                }
            }
        }

        // ---- phased: band (16 rows) -> gather/exp/sum for that mt
#pragma unroll
        for (int mt = 0; mt < 2; ++mt) {
            const int base = 48 - iter * 32 - mt * 16;   // >= 0 for all phases
            uint32_t pa[2];
            ldsm_x2(sptr(&psA[(iter * 32 + mt * 16 + (lane & 15)) * PEP]), pa[0], pa[1]);
#pragma unroll
            for (int tp = 0; tp < 2; ++tp) {
                const int tb = w * 4 + tp * 2;
                uint32_t b2[2];
                ldsm_x2(sptr(&peW[(base + tb * 8 + (lane & 15)) * PEP]), b2[0], b2[1]);
#pragma unroll
                for (int tt = 0; tt < 2; ++tt) {
                    const int nn = (tb + tt) * 8 + (lane & 3) * 2;
                    float bc[4] = {0.f, 0.f, 0.f, 0.f};
                    mma_f16_k8(bc, pa, b2[tt]);
                    const int r16 = lane >> 2;
                    *(uint32_t*)&band[r16 * BANDP + nn] =
                        h2u(__floats2half2_rn(bc[0], bc[1]));
                    *(uint32_t*)&band[(r16 + 8) * BANDP + nn] =
                        h2u(__floats2half2_rn(bc[2], bc[3]));
                }
            }
            if (w < 4) {                             // tiles 64..67
                const int t = 64 + w;
                uint32_t b1;
                ldsm_x1(sptr(&peW[(base + t * 8 + (lane & 7)) * PEP]), b1);
                const int nn = t * 8 + (lane & 3) * 2;
                float bc[4] = {0.f, 0.f, 0.f, 0.f};
                mma_f16_k8(bc, pa, b1);
                const int r16 = lane >> 2;
                *(uint32_t*)&band[r16 * BANDP + nn] =
                    h2u(__floats2half2_rn(bc[0], bc[1]));
                *(uint32_t*)&band[(r16 + 8) * BANDP + nn] =
                    h2u(__floats2half2_rn(bc[2], bc[3]));
            }
            __syncthreads();

            // epilogue for this mt: band read m = col + 15 - r16
#pragma unroll
            for (int cp = 0; cp < 2; ++cp) {
                const int rl = mt * 16 + cp * 8 + (lane >> 2);   // 0..31 within iter
                const int r16 = cp * 8 + (lane >> 2);            // 0..15
                float s = 0.f;
#pragma unroll
                for (int nt = 0; nt < 4; ++nt)
#pragma unroll
                    for (int cc = 0; cc < 2; ++cc) {
                        const int col = w * 32 + nt * 8 + (lane & 3) * 2 + cc;
                        float v = acc[mt][nt][cp * 2 + cc]
                                + __half2float(band[r16 * BANDP + col + 15 - r16]);
                        if (msk[col]) v = -1000.f;
                        v = __expf(v);
                        acc[mt][nt][cp * 2 + cc] = v;
                        s += v;
                    }
                s += __shfl_xor_sync(0xffffffffu, s, 1);
                s += __shfl_xor_sync(0xffffffffu, s, 2);
                if ((lane & 3) == 0) redS[rl * 16 + w] = s;
            }
            __syncthreads();
        }

        // ---- final row-sum reduce for this iter
        {
            float v = redS[tid];
            v += __shfl_xor_sync(0xffffffffu, v, 1);
            v += __shfl_xor_sync(0xffffffffu, v, 2);
            v += __shfl_xor_sync(0xffffffffu, v, 4);
            v += __shfl_xor_sync(0xffffffffu, v, 8);
            if ((tid & 15) == 0) ginv[tid >> 4] = 1.f / v;
        }
        __syncthreads();

        // ---- scale + streaming store for this iter
#pragma unroll
        for (int mt = 0; mt < 2; ++mt)
#pragma unroll
            for (int cp = 0; cp < 2; ++cp) {
                const int rl = mt * 16 + cp * 8 + (lane >> 2);
                const float iv = ginv[rl];
                const size_t base_o =
                    (((size_t)h * 64 + b) * 512 + t0b + iter * 32 + rl) * 512;
#pragma unroll
                for (int nt = 0; nt < 4; ++nt) {
                    float2 o;
                    o.x = acc[mt][nt][cp * 2 + 0] * iv;
                    o.y = acc[mt][nt][cp * 2 + 1] * iv;
                    __stcs((float2*)&out[base_o + w * 32 + nt * 8 + (lane & 3) * 2], o);
                }
            }
        __syncthreads();
    }
}

// ---------------------------------------------------------------------------
extern "C" void kernel_launch(void* const* d_in, const int* in_sizes, int n_in,
                              void* d_out, int out_size)
{
    const float* lm_pruned = (const float*)d_in[0];
    const float* am_pruned = (const float*)d_in[1];
    const float* pos_emb   = (const float*)d_in[2];
    const unsigned char* kpm = (const unsigned char*)d_in[3];
    const float* W_lm  = (const float*)d_in[4];
    const float* b_lm  = (const float*)d_in[5];
    const float* W_am  = (const float*)d_in[6];
    const float* b_am  = (const float*)d_in[7];
    const float* W_pos = (const float*)d_in[8];
    float* out = (float*)d_out;

    prep_kernel<<<96, 256>>>(W_lm, W_am);

    const int proj_smem = (2 * ASZ + 2 * BSZ) * 2 * 2;   // 102400 bytes
    cudaFuncSetAttribute(proj_mma3, cudaFuncAttributeMaxDynamicSharedMemorySize, proj_smem);
    proj_mma3<<<dim3(256, 3), 256, proj_smem>>>(lm_pruned, am_pruned, b_lm, b_am,
                                                pos_emb, W_pos);

    const int attn_smem = SM_HALVES * 2            // half arrays
                        + 512 * 4 + 32 * 4 + 512;  // redS, ginv, mask
    cudaFuncSetAttribute(attn_kernel, cudaFuncAttributeMaxDynamicSharedMemorySize, attn_smem);
    attn_kernel<<<dim3(8, 64, 5), 512, attn_smem>>>(kpm, out);
}

// round 17
// speedup vs baseline: 1.0684x; 1.0273x over previous
#include <cuda_runtime.h>
#include <cuda_fp16.h>
#include <cstdint>
#include <cstring>

// ---------------------------------------------------------------------------
// Shapes: T=S=512, B=64, D=512, H=5, QHD=32, PHD=4, PD=192
// fp16 hi/lo split intermediates in [b][t][col] layout.
// q and p are PRE-SCALED by log2e so attn logits live in the base-2 domain.
// ---------------------------------------------------------------------------
static __device__ __half g_qh[64 * 512 * 160];
static __device__ __half g_ql[64 * 512 * 160];
static __device__ __half g_kh[64 * 512 * 160];
static __device__ __half g_kl[64 * 512 * 160];
static __device__ __half g_ph[64 * 512 * 20];    // p (log2e-scaled), fp16
static __device__ __half g_peh[5 * 1023 * 8];    // pe, fp16, [h][n][8] padded
static __device__ __half g_wh[2 * 192 * 512];    // pre-split W, [which][n][k]
static __device__ __half g_wl[2 * 192 * 512];

#define LOG2E 1.4426950408889634f

__device__ __forceinline__ uint32_t h2u(__half2 v) {
    uint32_t u;
    memcpy(&u, &v, 4);
    return u;
}
__device__ __forceinline__ float ex2f(float x) {
    float r;
    asm("ex2.approx.f32 %0, %1;" : "=f"(r) : "f"(x));
    return r;
}
__device__ __forceinline__ uint32_t sptr(const void* p) {
    return (uint32_t)__cvta_generic_to_shared(p);
}
__device__ __forceinline__ void ldsm_x4(uint32_t a, uint32_t& r0, uint32_t& r1,
                                        uint32_t& r2, uint32_t& r3) {
    asm volatile("ldmatrix.sync.aligned.m8n8.x4.shared.b16 {%0,%1,%2,%3}, [%4];"
                 : "=r"(r0), "=r"(r1), "=r"(r2), "=r"(r3) : "r"(a));
}
__device__ __forceinline__ void ldsm_x2(uint32_t a, uint32_t& r0, uint32_t& r1) {
    asm volatile("ldmatrix.sync.aligned.m8n8.x2.shared.b16 {%0,%1}, [%2];"
                 : "=r"(r0), "=r"(r1) : "r"(a));
}
__device__ __forceinline__ void ldsm_x1(uint32_t a, uint32_t& r0) {
    asm volatile("ldmatrix.sync.aligned.m8n8.x1.shared.b16 {%0}, [%1];"
                 : "=r"(r0) : "r"(a));
}
__device__ __forceinline__ void mma_f16(float* c, const uint32_t* a, uint32_t b0, uint32_t b1) {
    asm volatile("mma.sync.aligned.m16n8k16.row.col.f32.f16.f16.f32 "
                 "{%0,%1,%2,%3},{%4,%5,%6,%7},{%8,%9},{%0,%1,%2,%3};"
                 : "+f"(c[0]), "+f"(c[1]), "+f"(c[2]), "+f"(c[3])
                 : "r"(a[0]), "r"(a[1]), "r"(a[2]), "r"(a[3]), "r"(b0), "r"(b1));
}
__device__ __forceinline__ void mma_f16_k8(float* c, const uint32_t* a, uint32_t b0) {
    asm volatile("mma.sync.aligned.m16n8k8.row.col.f32.f16.f16.f32 "
                 "{%0,%1,%2,%3},{%4,%5},{%6},{%0,%1,%2,%3};"
                 : "+f"(c[0]), "+f"(c[1]), "+f"(c[2]), "+f"(c[3])
                 : "r"(a[0]), "r"(a[1]), "r"(b0));
}
__device__ __forceinline__ void split_h(float x, __half& h, __half& l) {
    h = __float2half_rn(x);
    l = __float2half_rn(x - __half2float(h));
}
#define CP16(dst, src) asm volatile("cp.async.cg.shared.global [%0], [%1], 16;" \
                                    :: "r"(dst), "l"(src))

// ---------------------------------------------------------------------------
// Prep: W pre-split ONLY (96 blocks, 8 elements/thread).
// ---------------------------------------------------------------------------
__global__ __launch_bounds__(256)
void prep_kernel(const float* __restrict__ W_lm, const float* __restrict__ W_am)
{
    const int base = (blockIdx.x * 256 + threadIdx.x) * 8;
    float v[8];
#pragma unroll
    for (int i = 0; i < 8; ++i) {
        const int idx = base + i;
        const int which = idx / 98304;
        const int r = idx % 98304;
        const int k = r / 192, col = r % 192;
        v[i] = 0.f;
        if (which == 0) { if (col < 180) v[i] = W_lm[k * 180 + col]; }
        else            { if (col < 160) v[i] = W_am[k * 160 + col]; }
    }
#pragma unroll
    for (int i = 0; i < 8; ++i) {
        const int idx = base + i;
        const int which = idx / 98304;
        const int r = idx % 98304;
        const int k = r / 192, col = r % 192;
        __half h, l;
        split_h(v[i], h, l);
        const int o = which * 98304 + col * 512 + k;
        g_wh[o] = h;
        g_wl[o] = l;
    }
}

// ---------------------------------------------------------------------------
// Projection GEMM (fp16 3-term split). blockIdx.y: 0 = lm, 1 = am,
// 2 = pe projection (light blocks, hidden under the heavy GEMM blocks).
// q and p outputs are scaled by LOG2E in the epilogue.
// ---------------------------------------------------------------------------
#define PA 40
#define PBN 40
#define ASZ (128 * PA)
#define BSZ (192 * PBN)

__global__ __launch_bounds__(256)
void proj_mma3(const float* __restrict__ X_lm, const float* __restrict__ X_am,
               const float* __restrict__ b_lm, const float* __restrict__ b_am,
               const float* __restrict__ pos, const float* __restrict__ Wp)
{
    const int which = blockIdx.y;

    if (which == 2) {                      // ---- pe projection slice
        const int idx = blockIdx.x * 256 + threadIdx.x;
        if (idx >= 1023 * 20) return;
        const int n = idx / 20;
        const int c = idx % 20;
        float s = 0.f;
#pragma unroll 8
        for (int d = 0; d < 192; ++d)
            s = fmaf(pos[n * 192 + d], Wp[d * 20 + c], s);
        const int hh = c >> 2, dd = c & 3;
        g_peh[((size_t)hh * 1023 + n) * 8 + dd] = __float2half_rn(s);
        if (dd == 0)
            *(uint2*)&g_peh[((size_t)hh * 1023 + n) * 8 + 4] = make_uint2(0u, 0u);
        return;
    }

    extern __shared__ char sm[];
    __half* Ah = (__half*)sm;              // [2][ASZ]
    __half* Al = Ah + 2 * ASZ;
    __half* Bh = Al + 2 * ASZ;             // [2][BSZ]
    __half* Bl = Bh + 2 * BSZ;

    const float* X = which ? X_am : X_lm;
    const float* bias = which ? b_am : b_lm;
    const int N = which ? 160 : 180;
    const __half* Wh = g_wh + which * 98304;
    const __half* Wl = g_wl + which * 98304;

    const int tid = threadIdx.x;
    const int m0 = blockIdx.x * 128;
    const int w = tid >> 5, lane = tid & 31;
    const int wm = (w >> 1) * 32, wn = (w & 1) * 96;

    float4 aR[4];

    auto CPB = [&](int buf, int kt) {
#pragma unroll
        for (int i = 0; i < 3; ++i) {
            const int f = tid + 256 * i;          // < 768
            const int n = f >> 2, c = f & 3;
            CP16(sptr(&Bh[buf * BSZ + n * PBN + c * 8]), &Wh[n * 512 + kt + c * 8]);
            CP16(sptr(&Bl[buf * BSZ + n * PBN + c * 8]), &Wl[n * 512 + kt + c * 8]);
        }
    };
    auto LDGA = [&](int kt) {
#pragma unroll
        for (int i = 0; i < 4; ++i) {
            const int f = tid + 256 * i;
            aR[i] = *(const float4*)&X[(size_t)(m0 + (f >> 3)) * 512 + kt + (f & 7) * 4];
        }
    };
    auto STSA = [&](int buf) {
#pragma unroll
        for (int i = 0; i < 4; ++i) {
            const int f = tid + 256 * i;
            const int row = f >> 3, kc = (f & 7) * 4;
            __half h0, l0, h1, l1, h2, l2, h3, l3;
            split_h(aR[i].x, h0, l0); split_h(aR[i].y, h1, l1);
            split_h(aR[i].z, h2, l2); split_h(aR[i].w, h3, l3);
            *(ushort4*)&Ah[buf * ASZ + row * PA + kc] = make_ushort4(
                __half_as_ushort(h0), __half_as_ushort(h1),
                __half_as_ushort(h2), __half_as_ushort(h3));
            *(ushort4*)&Al[buf * ASZ + row * PA + kc] = make_ushort4(
                __half_as_ushort(l0), __half_as_ushort(l1),
                __half_as_ushort(l2), __half_as_ushort(l3));
        }
    };

    float acc[2][12][4];
#pragma unroll
    for (int mt = 0; mt < 2; ++mt)
#pragma unroll
        for (int nt = 0; nt < 12; ++nt)
#pragma unroll
            for (int c = 0; c < 4; ++c) acc[mt][nt][c] = 0.f;

    CPB(0, 0);
    asm volatile("cp.async.commit_group;");
    LDGA(0);
    STSA(0);
    asm volatile("cp.async.wait_group 0;");
    __syncthreads();

    for (int s = 0; s < 16; ++s) {
        const int cur = s & 1;
        if (s < 15) {
            CPB(cur ^ 1, (s + 1) * 32);
            asm volatile("cp.async.commit_group;");
            LDGA((s + 1) * 32);
        }
#pragma unroll
        for (int ks = 0; ks < 2; ++ks) {
            uint32_t ah[2][4], al[2][4];
#pragma unroll
            for (int mt = 0; mt < 2; ++mt) {
                const int ro = (wm + mt * 16 + (lane & 15)) * PA + ks * 16 + ((lane >> 4) & 1) * 8;
                ldsm_x4(sptr(&Ah[cur * ASZ + ro]), ah[mt][0], ah[mt][1], ah[mt][2], ah[mt][3]);
                ldsm_x4(sptr(&Al[cur * ASZ + ro]), al[mt][0], al[mt][1], al[mt][2], al[mt][3]);
            }
#pragma unroll
            for (int ntp = 0; ntp < 6; ++ntp) {
                uint32_t bh[4], bl[4];
                const int ro = (wn + ntp * 16 + (lane & 7) + ((lane >> 4) & 1) * 8) * PBN
                             + ks * 16 + ((lane >> 3) & 1) * 8;
                ldsm_x4(sptr(&Bh[cur * BSZ + ro]), bh[0], bh[1], bh[2], bh[3]);
                ldsm_x4(sptr(&Bl[cur * BSZ + ro]), bl[0], bl[1], bl[2], bl[3]);
#pragma unroll
                for (int sub = 0; sub < 2; ++sub) {
                    const int q = sub * 2;
#pragma unroll
                    for (int mt = 0; mt < 2; ++mt) {
                        float* a4 = acc[mt][ntp * 2 + sub];
                        mma_f16(a4, al[mt], bh[q], bh[q + 1]);
                        mma_f16(a4, ah[mt], bl[q], bl[q + 1]);
                        mma_f16(a4, ah[mt], bh[q], bh[q + 1]);
                    }
                }
            }
        }
        if (s < 15) {
            STSA(cur ^ 1);
            asm volatile("cp.async.wait_group 0;");
            __syncthreads();
        }
    }

    // ---- epilogue: bias add, (q,p scaled by LOG2E), split fp16, store
    const float oscale = (which == 0) ? LOG2E : 1.f;
#pragma unroll
    for (int mt = 0; mt < 2; ++mt) {
        const int r = m0 + wm + mt * 16 + (lane >> 2);
#pragma unroll
        for (int nt = 0; nt < 12; ++nt) {
            const int col = wn + nt * 8 + (lane & 3) * 2;
            if (col >= N) continue;
            const float b0 = bias[col], b1 = bias[col + 1];
            const float v[4] = {(acc[mt][nt][0] + b0) * oscale,
                                (acc[mt][nt][1] + b1) * oscale,
                                (acc[mt][nt][2] + b0) * oscale,
                                (acc[mt][nt][3] + b1) * oscale};
#pragma unroll
            for (int half_ = 0; half_ < 2; ++half_) {
                const int rr = r + half_ * 8;
                const int t = rr >> 6, bb = rr & 63;
                const float x0 = v[half_ * 2], x1 = v[half_ * 2 + 1];
                if (col < 160) {
                    const size_t o = ((size_t)(bb << 9) + t) * 160 + col;
                    __half h0, l0, h1, l1;
                    split_h(x0, h0, l0); split_h(x1, h1, l1);
                    if (which == 0) {
                        *(ushort2*)&g_qh[o] = make_ushort2(__half_as_ushort(h0), __half_as_ushort(h1));
                        *(ushort2*)&g_ql[o] = make_ushort2(__half_as_ushort(l0), __half_as_ushort(l1));
                    } else {
                        *(ushort2*)&g_kh[o] = make_ushort2(__half_as_ushort(h0), __half_as_ushort(h1));
                        *(ushort2*)&g_kl[o] = make_ushort2(__half_as_ushort(l0), __half_as_ushort(l1));
                    }
                } else if (which == 0) {
                    *(__half2*)&g_ph[((size_t)(bb << 9) + t) * 20 + col - 160] =
                        __floats2half2_rn(x0, x1);
                }
            }
        }
    }
}

// ---------------------------------------------------------------------------
// Attention weights. Block = one 64x512 tile of one (b,h). Grid (8,64,5).
// Logits arrive pre-scaled by log2e -> raw ex2 in the epilogue, no FMUL.
// Per-thread 8-col mask byte precomputed once; common path has ZERO
// per-element mask work. Streaming output stores. ~104.6 KB smem, occ 2.
// ---------------------------------------------------------------------------
#define PEP 8
#define BANDP 552
#define PEROWS2 592

#define SWZ(r, c) ((c) ^ (((r) >> 1) & 3))

// smem layout in halves
#define SM_KH   0
#define SM_KL   (512 * 32)
#define SM_QH   (2 * 512 * 32)
#define SM_QL   (2 * 512 * 32 + 64 * 32)
#define SM_PEW  (2 * 512 * 32 + 2 * 64 * 32)
#define SM_PSA  (SM_PEW + PEROWS2 * PEP)
#define SM_BAND (SM_PSA + 64 * PEP)
#define SM_HALVES (SM_BAND + 16 * BANDP)

__global__ __launch_bounds__(512, 2)
void attn_kernel(const unsigned char* __restrict__ mask, float* __restrict__ out)
{
    extern __shared__ __half sh[];
    __half* Kh   = sh + SM_KH;
    __half* Kl   = sh + SM_KL;
    __half* Qh   = sh + SM_QH;                        // [64][32]
    __half* Ql   = sh + SM_QL;
    __half* peW  = sh + SM_PEW;                       // [592][8]
    __half* psA  = sh + SM_PSA;                       // [64][8]
    __half* band = sh + SM_BAND;                      // [16][BANDP], phased
    float* redS  = (float*)(sh + SM_HALVES);          // [32][16]
    float* ginv  = redS + 512;                        // [32]
    unsigned char* msk = (unsigned char*)(ginv + 32); // [512]

    const int t0b = blockIdx.x * 64;
    const int b   = blockIdx.y;
    const int h   = blockIdx.z;
    const int tid = threadIdx.x;
    const int w = tid >> 5, lane = tid & 31;

    // ---- one-shot load phase: K + pe via cp.async, Q (both halves), p, mask
#pragma unroll
    for (int s = 0; s < 4; ++s) {
        const int it = tid + 512 * s;               // 0..2047
        const int j = it >> 2, c = it & 3;
        const __half* srcH = g_kh + ((size_t)(b << 9) + j) * 160 + h * 32 + c * 8;
        const __half* srcL = g_kl + ((size_t)(b << 9) + j) * 160 + h * 32 + c * 8;
        CP16(sptr(&Kh[j * 32 + SWZ(j, c) * 8]), srcH);
        CP16(sptr(&Kl[j * 32 + SWZ(j, c) * 8]), srcL);
    }
    for (int j = tid; j < PEROWS2; j += 512) {
        const int n = 448 - t0b + j;                // >= 0 always
        if (n <= 1022) {
            CP16(sptr(&peW[j * PEP]), g_peh + ((size_t)h * 1023 + n) * 8);
        } else {
            *(uint4*)&peW[j * PEP] = make_uint4(0u, 0u, 0u, 0u);
        }
    }
    asm volatile("cp.async.commit_group;");

    {   // Q: 2 parts x 64 rows x 4 chunks = 512 assignments
        const int part = tid >> 8, r = (tid >> 2) & 63, c = tid & 3;
        const size_t o = ((size_t)(b << 9) + t0b + r) * 160 + h * 32 + c * 8;
        __half* dst = part ? Ql : Qh;
        const __half* src = part ? g_ql : g_qh;
        *(uint4*)&dst[r * 32 + SWZ(r, c) * 8] = *(const uint4*)(src + o);
    }
    if (tid < 64) {
        const uint2 u = *(const uint2*)&g_ph[((size_t)(b << 9) + t0b + tid) * 20 + h * 4];
        *(uint4*)&psA[tid * PEP] = make_uint4(u.x, u.y, 0u, 0u);
    }
    msk[tid & 511] = mask[b * 512 + (tid & 511)];
    asm volatile("cp.async.wait_group 0;");
    __syncthreads();

    // ---- per-thread mask byte for this thread's 8 columns (reused all iters)
    unsigned int mbits = 0;
    {
        const int c0 = (lane & 3) * 2;
#pragma unroll
        for (int nt = 0; nt < 4; ++nt) {
            mbits |= (unsigned)msk[w * 32 + nt * 8 + c0]     << (nt * 2);
            mbits |= (unsigned)msk[w * 32 + nt * 8 + c0 + 1] << (nt * 2 + 1);
        }
    }

#pragma unroll 1
    for (int iter = 0; iter < 2; ++iter) {
        // ---- content QK^T (fp16 3-term), swizzled ldmatrix
        float acc[2][4][4];
#pragma unroll
        for (int mt = 0; mt < 2; ++mt)
#pragma unroll
            for (int nt = 0; nt < 4; ++nt)
#pragma unroll
                for (int c = 0; c < 4; ++c) acc[mt][nt][c] = 0.f;

#pragma unroll
        for (int ks = 0; ks < 2; ++ks) {
            uint32_t ah[2][4], al[2][4];
#pragma unroll
            for (int mt = 0; mt < 2; ++mt) {
                const int row = iter * 32 + mt * 16 + (lane & 15);
                const int ch = ks * 2 + ((lane >> 4) & 1);
                const int ro = row * 32 + SWZ(row, ch) * 8;
                ldsm_x4(sptr(&Qh[ro]), ah[mt][0], ah[mt][1], ah[mt][2], ah[mt][3]);
                ldsm_x4(sptr(&Ql[ro]), al[mt][0], al[mt][1], al[mt][2], al[mt][3]);
            }
#pragma unroll
            for (int ntp = 0; ntp < 2; ++ntp) {
                uint32_t bh[4], bl[4];
                const int row = w * 32 + ntp * 16 + (lane & 7) + ((lane >> 4) & 1) * 8;
                const int ch = ks * 2 + ((lane >> 3) & 1);
                const int ro = row * 32 + SWZ(row, ch) * 8;
                ldsm_x4(sptr(&Kh[ro]), bh[0], bh[1], bh[2], bh[3]);
                ldsm_x4(sptr(&Kl[ro]), bl[0], bl[1], bl[2], bl[3]);
#pragma unroll
                for (int sub = 0; sub < 2; ++sub) {
                    const int q = sub * 2;
#pragma unroll
                    for (int mt = 0; mt < 2; ++mt) {
                        float* a4 = acc[mt][ntp * 2 + sub];
                        mma_f16(a4, al[mt], bh[q], bh[q + 1]);
                        mma_f16(a4, ah[mt], bl[q], bl[q + 1]);
                        mma_f16(a4, ah[mt], bh[q], bh[q + 1]);
                    }
                }
            }
        }

        // ---- phased: band (16 rows) -> gather/ex2/sum for that mt
#pragma unroll
        for (int mt = 0; mt < 2; ++mt) {
            const int base = 48 - iter * 32 - mt * 16;   // >= 0 for all phases
            uint32_t pa[2];
            ldsm_x2(sptr(&psA[(iter * 32 + mt * 16 + (lane & 15)) * PEP]), pa[0], pa[1]);
#pragma unroll
            for (int tp = 0; tp < 2; ++tp) {
                const int tb = w * 4 + tp * 2;
                uint32_t b2[2];
                ldsm_x2(sptr(&peW[(base + tb * 8 + (lane & 15)) * PEP]), b2[0], b2[1]);
#pragma unroll
                for (int tt = 0; tt < 2; ++tt) {
                    const int nn = (tb + tt) * 8 + (lane & 3) * 2;
                    float bc[4] = {0.f, 0.f, 0.f, 0.f};
                    mma_f16_k8(bc, pa, b2[tt]);
                    const int r16 = lane >> 2;
                    *(uint32_t*)&band[r16 * BANDP + nn] =
                        h2u(__floats2half2_rn(bc[0], bc[1]));
                    *(uint32_t*)&band[(r16 + 8) * BANDP + nn] =
                        h2u(__floats2half2_rn(bc[2], bc[3]));
                }
            }
            if (w < 4) {                             // tiles 64..67
                const int t = 64 + w;
                uint32_t b1;
                ldsm_x1(sptr(&peW[(base + t * 8 + (lane & 7)) * PEP]), b1);
                const int nn = t * 8 + (lane & 3) * 2;
                float bc[4] = {0.f, 0.f, 0.f, 0.f};
                mma_f16_k8(bc, pa, b1);
                const int r16 = lane >> 2;
                *(uint32_t*)&band[r16 * BANDP + nn] =
                    h2u(__floats2half2_rn(bc[0], bc[1]));
                *(uint32_t*)&band[(r16 + 8) * BANDP + nn] =
                    h2u(__floats2half2_rn(bc[2], bc[3]));
            }
            __syncthreads();

            // epilogue for this mt: band read m = col + 15 - r16; raw ex2
#pragma unroll
            for (int cp = 0; cp < 2; ++cp) {
                const int rl = mt * 16 + cp * 8 + (lane >> 2);   // 0..31 within iter
                const int r16 = cp * 8 + (lane >> 2);            // 0..15
                float s = 0.f;
                if (mbits == 0u) {                               // common fast path
#pragma unroll
                    for (int nt = 0; nt < 4; ++nt)
#pragma unroll
                        for (int cc = 0; cc < 2; ++cc) {
                            const int col = w * 32 + nt * 8 + (lane & 3) * 2 + cc;
                            float v = acc[mt][nt][cp * 2 + cc]
                                    + __half2float(band[r16 * BANDP + col + 15 - r16]);
                            v = ex2f(v);
                            acc[mt][nt][cp * 2 + cc] = v;
                            s += v;
                        }
                } else {
#pragma unroll
                    for (int nt = 0; nt < 4; ++nt)
#pragma unroll
                        for (int cc = 0; cc < 2; ++cc) {
                            const int col = w * 32 + nt * 8 + (lane & 3) * 2 + cc;
                            float v = acc[mt][nt][cp * 2 + cc]
                                    + __half2float(band[r16 * BANDP + col + 15 - r16]);
                            if (mbits & (1u << (nt * 2 + cc))) v = -1443.f;
                            v = ex2f(v);
                            acc[mt][nt][cp * 2 + cc] = v;
                            s += v;
                        }
                }
                s += __shfl_xor_sync(0xffffffffu, s, 1);
                s += __shfl_xor_sync(0xffffffffu, s, 2);
                if ((lane & 3) == 0) redS[rl * 16 + w] = s;
            }
            __syncthreads();
        }

        // ---- final row-sum reduce for this iter
        {
            float v = redS[tid];
            v += __shfl_xor_sync(0xffffffffu, v, 1);
            v += __shfl_xor_sync(0xffffffffu, v, 2);
            v += __shfl_xor_sync(0xffffffffu, v, 4);
            v += __shfl_xor_sync(0xffffffffu, v, 8);
            if ((tid & 15) == 0) ginv[tid >> 4] = 1.f / v;
        }
        __syncthreads();

        // ---- scale + streaming store for this iter
#pragma unroll
        for (int mt = 0; mt < 2; ++mt)
#pragma unroll
            for (int cp = 0; cp < 2; ++cp) {
                const int rl = mt * 16 + cp * 8 + (lane >> 2);
                const float iv = ginv[rl];
                const size_t base_o =
                    (((size_t)h * 64 + b) * 512 + t0b + iter * 32 + rl) * 512;
#pragma unroll
                for (int nt = 0; nt < 4; ++nt) {
                    float2 o;
                    o.x = acc[mt][nt][cp * 2 + 0] * iv;
                    o.y = acc[mt][nt][cp * 2 + 1] * iv;
                    __stcs((float2*)&out[base_o + w * 32 + nt * 8 + (lane & 3) * 2], o);
                }
            }
        __syncthreads();
    }
}

// ---------------------------------------------------------------------------
extern "C" void kernel_launch(void* const* d_in, const int* in_sizes, int n_in,
                              void* d_out, int out_size)
{
    const float* lm_pruned = (const float*)d_in[0];
    const float* am_pruned = (const float*)d_in[1];
    const float* pos_emb   = (const float*)d_in[2];
    const unsigned char* kpm = (const unsigned char*)d_in[3];
    const float* W_lm  = (const float*)d_in[4];
    const float* b_lm  = (const float*)d_in[5];
    const float* W_am  = (const float*)d_in[6];
    const float* b_am  = (const float*)d_in[7];
    const float* W_pos = (const float*)d_in[8];
    float* out = (float*)d_out;

    prep_kernel<<<96, 256>>>(W_lm, W_am);

    const int proj_smem = (2 * ASZ + 2 * BSZ) * 2 * 2;   // 102400 bytes
    cudaFuncSetAttribute(proj_mma3, cudaFuncAttributeMaxDynamicSharedMemorySize, proj_smem);
    proj_mma3<<<dim3(256, 3), 256, proj_smem>>>(lm_pruned, am_pruned, b_lm, b_am,
                                                pos_emb, W_pos);

    const int attn_smem = SM_HALVES * 2            // half arrays
                        + 512 * 4 + 32 * 4 + 512;  // redS, ginv, mask
    cudaFuncSetAttribute(attn_kernel, cudaFuncAttributeMaxDynamicSharedMemorySize, attn_smem);
    attn_kernel<<<dim3(8, 64, 5), 512, attn_smem>>>(kpm, out);
}